// round 17
// baseline (speedup 1.0000x reference)
#include <cuda_runtime.h>
#include <cuda_fp16.h>
#include <cstdint>

#define U_   32768
#define EPSF 1e-6f

// ---------------- scratch globals ----------------
__device__ int   g_count;
__device__ int   g_idx[U_];
__device__ float g_sum2[U_], g_sumsq2[U_];          // compacted
__device__ float g_h1[(size_t)U_ * 512];            // compacted rows, f32
__device__ __half g_af[(size_t)U_ * 512];           // compacted relu(LN1(z)), fp16
__device__ __half g_a2f[(size_t)U_ * 512];          // compacted relu(LN2(h1)), fp16
__device__ float g_grid[64 * 64 * 256];
__device__ __half g_gf[64 * 64 * 256];              // post-LN3 acts, fp16
__device__ __half g_w1f[512 * 512];                 // [n][k]
__device__ __half g_w2f[256 * 512];                 // [n][k]
__device__ __half g_wcf[9 * 256 * 256];             // [tap][co][ci]

// ---------------- helpers ----------------
__device__ __forceinline__ uint32_t smem_u32(const void* p) {
    uint32_t a;
    asm("{ .reg .u64 t; cvta.to.shared.u64 t, %1; cvt.u32.u64 %0, t; }" : "=r"(a) : "l"(p));
    return a;
}
__device__ __forceinline__ void cpa16(uint32_t d, const void* s) {
    asm volatile("cp.async.cg.shared.global [%0], [%1], 16;" :: "r"(d), "l"(s));
}
__device__ __forceinline__ void cpa16z(uint32_t d, const void* s, int sz) {
    asm volatile("cp.async.ca.shared.global [%0], [%1], 16, %2;" :: "r"(d), "l"(s), "r"(sz));
}
__device__ __forceinline__ void cpa_commit() { asm volatile("cp.async.commit_group;" ::: "memory"); }
__device__ __forceinline__ void cpa_wait0()  { asm volatile("cp.async.wait_group 0;"  ::: "memory"); }
__device__ __forceinline__ void ldx4(uint32_t* r, uint32_t a) {
    asm volatile("ldmatrix.sync.aligned.m8n8.x4.shared.b16 {%0,%1,%2,%3}, [%4];"
                 : "=r"(r[0]), "=r"(r[1]), "=r"(r[2]), "=r"(r[3]) : "r"(a));
}
__device__ __forceinline__ void mma_f16(float* c, const uint32_t* a, const uint32_t* b) {
    asm volatile(
        "mma.sync.aligned.m16n8k16.row.col.f32.f16.f16.f32 "
        "{%0,%1,%2,%3}, {%4,%5,%6,%7}, {%8,%9}, {%0,%1,%2,%3};"
        : "+f"(c[0]), "+f"(c[1]), "+f"(c[2]), "+f"(c[3])
        : "r"(a[0]), "r"(a[1]), "r"(a[2]), "r"(a[3]), "r"(b[0]), "r"(b[1]));
}

// ---------------- fused setup ----------------
__global__ void setup_kernel(const float* __restrict__ W1, const float* __restrict__ W2,
                             const float* __restrict__ cw) {
    int b = blockIdx.x, t = threadIdx.x;
    if (b < 1024) {
        ((float4*)g_grid)[b * 256 + t] = make_float4(0, 0, 0, 0);
    } else if (b < 1088) {
        int i = (b - 1024) * 256 + t;
        if (i < 8192) ((float4*)g_sum2)[i] = make_float4(0, 0, 0, 0);
        else ((float4*)g_sumsq2)[i - 8192] = make_float4(0, 0, 0, 0);
    } else if (b < 1120) {
        ((int4*)g_idx)[(b - 1088) * 256 + t] = make_int4(0, 0, 0, 0);
    } else if (b < 1121) {
        if (t == 0) g_count = 0;
    } else if (b < 2145) {                            // W1 [k][n] -> fp16 [n][k]
        int i = (b - 1121) * 256 + t;
        int n = i >> 9, k = i & 511;
        g_w1f[(size_t)n * 512 + k] = __float2half_rn(W1[(size_t)k * 512 + n]);
    } else if (b < 2657) {                            // W2 [k][n] -> fp16 [n][k]
        int i = (b - 2145) * 256 + t;
        int n = i >> 9, k = i & 511;
        g_w2f[(size_t)n * 512 + k] = __float2half_rn(W2[(size_t)k * 256 + n]);
    } else {                                          // conv w [tap][ci][co] -> fp16 [tap][co][ci]
        int i = (b - 2657) * 256 + t;
        int tap = i >> 16, r = i & 65535, co = r >> 8, ci = r & 255;
        g_wcf[(size_t)tap * 65536 + co * 256 + ci] =
            __float2half_rn(cw[((size_t)tap * 256 + ci) * 256 + co]);
    }
}

// ---------------- compaction + LN1 stats + fp16 A1 conversion ----------------
__global__ void compact_stats_kernel(const float* __restrict__ z, const int* __restrict__ ne,
                                     const float* __restrict__ lnS, const float* __restrict__ lnB) {
    int row = blockIdx.x;
    if (ne[row] == 0) return;
    __shared__ int spos;
    if (threadIdx.x == 0) spos = atomicAdd(&g_count, 1);
    float4 v = ((const float4*)(z + (size_t)row * 512))[threadIdx.x];
    float s = v.x + v.y + v.z + v.w;
    float q = v.x * v.x + v.y * v.y + v.z * v.z + v.w * v.w;
#pragma unroll
    for (int o = 16; o > 0; o >>= 1) {
        s += __shfl_down_sync(~0u, s, o); q += __shfl_down_sync(~0u, q, o);
    }
    __shared__ float ws[4], wq[4];
    __shared__ float sm_, sr_;
    if ((threadIdx.x & 31) == 0) { ws[threadIdx.x >> 5] = s; wq[threadIdx.x >> 5] = q; }
    __syncthreads();
    if (threadIdx.x == 0) {
        s = ws[0] + ws[1] + ws[2] + ws[3]; q = wq[0] + wq[1] + wq[2] + wq[3];
        float m = s / 512.f, var = q / 512.f - m * m;
        sm_ = m; sr_ = rsqrtf(var + EPSF);
        g_idx[spos] = row;
    }
    __syncthreads();
    int pos = spos;
    float m = sm_, rs = sr_;
    int k = threadIdx.x * 4;
    float4 sv = *(const float4*)(lnS + k);
    float4 bv = *(const float4*)(lnB + k);
    float a0 = fmaxf((v.x - m) * rs * sv.x + bv.x, 0.f);
    float a1 = fmaxf((v.y - m) * rs * sv.y + bv.y, 0.f);
    float a2 = fmaxf((v.z - m) * rs * sv.z + bv.z, 0.f);
    float a3 = fmaxf((v.w - m) * rs * sv.w + bv.w, 0.f);
    __half2 h01 = __floats2half2_rn(a0, a1);
    __half2 h23 = __floats2half2_rn(a2, a3);
    uint2 pk = make_uint2(*(uint32_t*)&h01, *(uint32_t*)&h23);
    ((uint2*)(g_af + (size_t)pos * 512))[threadIdx.x] = pk;
}

// ---------------- LN2 + relu + fp16 convert (prepass between gemm1 and gemm2) ----------------
__global__ void ln2cvt_kernel(const float* __restrict__ lnS, const float* __restrict__ lnB) {
    int r = blockIdx.x;
    if (r >= g_count) return;
    float s = g_sum2[r] * (1.f / 512.f), q = g_sumsq2[r] * (1.f / 512.f);
    float m = s, rs = rsqrtf(q - s * s + EPSF);
    int k = threadIdx.x * 4;
    float4 v = *(const float4*)(g_h1 + (size_t)r * 512 + k);
    float4 sv = *(const float4*)(lnS + k);
    float4 bv = *(const float4*)(lnB + k);
    float a0 = fmaxf((v.x - m) * rs * sv.x + bv.x, 0.f);
    float a1 = fmaxf((v.y - m) * rs * sv.y + bv.y, 0.f);
    float a2 = fmaxf((v.z - m) * rs * sv.z + bv.z, 0.f);
    float a3 = fmaxf((v.w - m) * rs * sv.w + bv.w, 0.f);
    __half2 h01 = __floats2half2_rn(a0, a1);
    __half2 h23 = __floats2half2_rn(a2, a3);
    uint2 pk = make_uint2(*(uint32_t*)&h01, *(uint32_t*)&h23);
    ((uint2*)(g_a2f + (size_t)r * 512))[threadIdx.x] = pk;
}

// ---------------- tiles: M=64, N=128, BK=64 fp16; 256 threads, 8 warps (2Mx4N, warp 32x32) ----------------
#define PBY 144
#define T_A 0
#define T_B (64 * PBY)                  // 9216
#define T_STG (T_B + 128 * PBY)         // 27648
#define T_SMEM (2 * T_STG)              // 55296
#define G_NCH 8
#define C_NCH 36

// Single-pass fp16 MMA over one K16 step: 8 independent MMAs.
#define MMA_K16(curB)                                                                          \
    {                                                                                          \
        uint32_t ah[2][4], bh[2][4];                                                           \
        _Pragma("unroll")                                                                      \
        for (int i = 0; i < 2; i++) {                                                          \
            uint32_t ra = (uint32_t)(wm + i * 16 + lr8 + (lg & 1) * 8) * PBY                   \
                        + (k0 + (lg >> 1) * 8) * 2;                                            \
            ldx4(ah[i], (curB) + T_A + ra);                                                    \
        }                                                                                      \
        _Pragma("unroll")                                                                      \
        for (int j = 0; j < 2; j++) {                                                          \
            uint32_t rb = (uint32_t)(wn + j * 16 + lr8 + (lg >> 1) * 8) * PBY                  \
                        + (k0 + (lg & 1) * 8) * 2;                                             \
            ldx4(bh[j], (curB) + T_B + rb);                                                    \
        }                                                                                      \
        _Pragma("unroll")                                                                      \
        for (int i = 0; i < 2; i++)                                                            \
            _Pragma("unroll")                                                                  \
            for (int j = 0; j < 2; j++) {                                                      \
                mma_f16(acc[i][2*j],     ah[i], bh[j]);                                        \
                mma_f16(acc[i][2*j + 1], ah[i], bh[j] + 2);                                    \
            }                                                                                  \
    }

template <int MODE>
__global__ void __launch_bounds__(256, 2)
gemm_mma(const float* __restrict__ bias,
         const int* __restrict__ ux, const int* __restrict__ uy) {
    int cnt = g_count;
    int cntPad = (cnt + 63) & ~63;
    int rowBase = blockIdx.y * 64;
    if (rowBase >= cntPad) return;

    extern __shared__ char smv[];
    uint32_t sb = smem_u32(smv);
    int tid = threadIdx.x, wid = tid >> 5, lane = tid & 31;
    int nBase = blockIdx.x * 128;
    const __half* Wf = (MODE == 0) ? g_w1f : g_w2f;
    const __half* Af = (MODE == 0) ? g_af  : g_a2f;

    // A producer: pure async fp16 path for both modes
    int arow = tid >> 2, q = tid & 3;
    int gr = rowBase + arow;
    uint32_t dA = arow * PBY + q * 32;            // 16 halfs = 32B per thread
    const char* srcA = (const char*)(Af + (size_t)gr * 512) + q * 32;
    // B producer: thread -> (n row, 32-half half-row)
    int bn = tid >> 1, bhf = tid & 1;
    const char* srcB = (const char*)(Wf + (size_t)(nBase + bn) * 512) + bhf * 64;
    uint32_t dB = T_B + bn * PBY + bhf * 64;

    float acc[2][4][4];
#pragma unroll
    for (int i = 0; i < 2; i++)
#pragma unroll
        for (int j = 0; j < 4; j++)
#pragma unroll
            for (int e = 0; e < 4; e++) acc[i][j][e] = 0.f;

    int wm = (wid >> 2) * 32, wn = (wid & 3) * 32;
    int lg = lane >> 3, lr8 = lane & 7;

    // prologue: chunk 0 -> stage 0
    {
#pragma unroll
        for (int j2 = 0; j2 < 4; j2++) cpa16(sb + dB + j2 * 16, srcB + j2 * 16);
        cpa16(sb + T_A + dA,      srcA);
        cpa16(sb + T_A + dA + 16, srcA + 16);
        cpa_commit(); cpa_wait0(); __syncthreads();
    }

    for (int c = 0; c < G_NCH; c++) {
        int cur = c & 1;
        uint32_t curB = sb + cur * T_STG, nxtB = sb + (cur ^ 1) * T_STG;
        if (c + 1 < G_NCH) {
#pragma unroll
            for (int j2 = 0; j2 < 4; j2++)
                cpa16(nxtB + dB + j2 * 16, srcB + (c + 1) * 128 + j2 * 16);
            cpa16(nxtB + T_A + dA,      srcA + (c + 1) * 128);
            cpa16(nxtB + T_A + dA + 16, srcA + (c + 1) * 128 + 16);
        }
#pragma unroll
        for (int ks = 0; ks < 4; ks++) {
            int k0 = ks * 16;
            MMA_K16(curB)
        }
        cpa_commit(); cpa_wait0(); __syncthreads();
    }

    // ---- epilogue ----
    int elr = lane >> 2, elc = (lane & 3) * 2;
#pragma unroll
    for (int i = 0; i < 2; i++) {
        int r0 = rowBase + wm + i * 16 + elr;
        int r1 = r0 + 8;
        if (MODE == 0) {
            float s0 = 0, q0 = 0, s1 = 0, q1 = 0;
#pragma unroll
            for (int jt = 0; jt < 4; jt++) {
                int col = nBase + wn + jt * 8 + elc;
                float b0 = __ldg(bias + col), b1 = __ldg(bias + col + 1);
                float d0 = acc[i][jt][0] + b0, d1 = acc[i][jt][1] + b1;
                float d2 = acc[i][jt][2] + b0, d3 = acc[i][jt][3] + b1;
                *(float2*)(g_h1 + (size_t)r0 * 512 + col) = make_float2(d0, d1);
                *(float2*)(g_h1 + (size_t)r1 * 512 + col) = make_float2(d2, d3);
                s0 += d0 + d1; q0 += d0 * d0 + d1 * d1;
                s1 += d2 + d3; q1 += d2 * d2 + d3 * d3;
            }
#pragma unroll
            for (int o = 1; o < 4; o <<= 1) {
                s0 += __shfl_xor_sync(~0u, s0, o); q0 += __shfl_xor_sync(~0u, q0, o);
                s1 += __shfl_xor_sync(~0u, s1, o); q1 += __shfl_xor_sync(~0u, q1, o);
            }
            if ((lane & 3) == 0) {
                atomicAdd(&g_sum2[r0], s0); atomicAdd(&g_sumsq2[r0], q0);
                atomicAdd(&g_sum2[r1], s1); atomicAdd(&g_sumsq2[r1], q1);
            }
        } else {
            int c0 = -1, c1 = -1;
            if (r0 < cnt) { int o0 = g_idx[r0]; c0 = (uy[o0] * 64 + ux[o0]) * 256; }
            if (r1 < cnt) { int o1 = g_idx[r1]; c1 = (uy[o1] * 64 + ux[o1]) * 256; }
#pragma unroll
            for (int jt = 0; jt < 4; jt++) {
                int col = nBase + wn + jt * 8 + elc;
                float b0 = __ldg(bias + col), b1 = __ldg(bias + col + 1);
                if (c0 >= 0) {
                    atomicAdd(&g_grid[c0 + col],     acc[i][jt][0] + b0);
                    atomicAdd(&g_grid[c0 + col + 1], acc[i][jt][1] + b1);
                }
                if (c1 >= 0) {
                    atomicAdd(&g_grid[c1 + col],     acc[i][jt][2] + b0);
                    atomicAdd(&g_grid[c1 + col + 1], acc[i][jt][3] + b1);
                }
            }
        }
    }
}

// ---------------- LN3 + relu + fp16 convert ----------------
__global__ void ln3_kernel(const float* __restrict__ s3, const float* __restrict__ b3) {
    int cell = blockIdx.x, t = threadIdx.x;
    float v = g_grid[(size_t)cell * 256 + t];
    float s = v, q = v * v;
#pragma unroll
    for (int o = 16; o > 0; o >>= 1) {
        s += __shfl_down_sync(~0u, s, o); q += __shfl_down_sync(~0u, q, o);
    }
    __shared__ float ws[8], wq[8]; __shared__ float sm_, sr_;
    if ((t & 31) == 0) { ws[t >> 5] = s; wq[t >> 5] = q; }
    __syncthreads();
    if (t == 0) {
        s = 0; q = 0;
#pragma unroll
        for (int i = 0; i < 8; i++) { s += ws[i]; q += wq[i]; }
        float m = s / 256.f;
        sm_ = m; sr_ = rsqrtf(q / 256.f - m * m + EPSF);
    }
    __syncthreads();
    float g = fmaxf((v - sm_) * sr_ * s3[t] + b3[t], 0.f);
    g_gf[(size_t)cell * 256 + t] = __float2half_rn(g);
}

// ---------------- conv via mma.sync (implicit GEMM), fp16 single-pass ----------------
__global__ void __launch_bounds__(256, 2)
conv_mma(const float* __restrict__ cbias, float* __restrict__ outp) {
    extern __shared__ char smv[];
    uint32_t sb = smem_u32(smv);
    int tid = threadIdx.x, wid = tid >> 5, lane = tid & 31;
    int coBase = blockIdx.x * 128;
    int y = blockIdx.y;
    int arow = tid >> 2, q = tid & 3;   // arow = x cell
    int bn = tid >> 1, bhf = tid & 1;

    float acc[2][4][4];
#pragma unroll
    for (int i = 0; i < 2; i++)
#pragma unroll
        for (int j = 0; j < 4; j++)
#pragma unroll
            for (int e = 0; e < 4; e++) acc[i][j][e] = 0.f;

    int wm = (wid >> 2) * 32, wn = (wid & 3) * 32;
    int lg = lane >> 3, lr8 = lane & 7;

    auto issue = [&](int c, uint32_t stB) {
        int tap = c >> 2, kc = (c & 3) * 64;
        int ky = tap / 3, kx = tap - ky * 3;
        int sy = y + ky - 1, sx = arow + kx - 1;
        bool ok = ((unsigned)sy < 64u) && ((unsigned)sx < 64u);
        size_t aoff = ((size_t)(ok ? (sy * 64 + sx) : 0)) * 256 + kc + q * 16;   // halfs
        const char* sh = (const char*)(g_gf + aoff);
        uint32_t dA = stB + T_A + arow * PBY + q * 32;
        int sz = ok ? 16 : 0;
        cpa16z(dA,      sh,      sz);
        cpa16z(dA + 16, sh + 16, sz);
        size_t boff = (size_t)tap * 65536 + (size_t)(coBase + bn) * 256 + kc + bhf * 32; // halfs
        const char* bsrc = (const char*)(g_wcf + boff);
        uint32_t dB = stB + T_B + bn * PBY + bhf * 64;
#pragma unroll
        for (int j2 = 0; j2 < 4; j2++) cpa16(dB + j2 * 16, bsrc + j2 * 16);
    };

    issue(0, sb);
    cpa_commit(); cpa_wait0(); __syncthreads();

    for (int c = 0; c < C_NCH; c++) {
        int cur = c & 1;
        uint32_t curB = sb + cur * T_STG;
        if (c + 1 < C_NCH) issue(c + 1, sb + (cur ^ 1) * T_STG);
#pragma unroll
        for (int ks = 0; ks < 4; ks++) {
            int k0 = ks * 16;
            MMA_K16(curB)
        }
        cpa_commit(); cpa_wait0(); __syncthreads();
    }

    int elr = lane >> 2, elc = (lane & 3) * 2;
#pragma unroll
    for (int i = 0; i < 2; i++) {
        int x0 = wm + i * 16 + elr, x1 = x0 + 8;
#pragma unroll
        for (int jt = 0; jt < 4; jt++) {
            int col = coBase + wn + jt * 8 + elc;
            float b0 = __ldg(cbias + col), b1 = __ldg(cbias + col + 1);
            *(float2*)(outp + ((size_t)(y * 64 + x0)) * 256 + col) =
                make_float2(acc[i][jt][0] + b0, acc[i][jt][1] + b1);
            *(float2*)(outp + ((size_t)(y * 64 + x1)) * 256 + col) =
                make_float2(acc[i][jt][2] + b0, acc[i][jt][3] + b1);
        }
    }
}

// ---------------- launch ----------------
extern "C" void kernel_launch(void* const* d_in, const int* in_sizes, int n_in,
                              void* d_out, int out_size) {
    const float* z     = (const float*)d_in[0];
    const int*   ux    = (const int*)d_in[1];
    const int*   uy    = (const int*)d_in[2];
    const int*   ne    = (const int*)d_in[3];
    const float* ln1_s = (const float*)d_in[4];
    const float* ln1_b = (const float*)d_in[5];
    const float* W1    = (const float*)d_in[6];
    const float* b1    = (const float*)d_in[7];
    const float* ln2_s = (const float*)d_in[8];
    const float* ln2_b = (const float*)d_in[9];
    const float* W2    = (const float*)d_in[10];
    const float* b2    = (const float*)d_in[11];
    const float* ln3_s = (const float*)d_in[12];
    const float* ln3_b = (const float*)d_in[13];
    const float* cw    = (const float*)d_in[14];
    const float* cb    = (const float*)d_in[15];
    float* out = (float*)d_out;
    (void)in_sizes; (void)n_in; (void)out_size;

    cudaFuncSetAttribute(gemm_mma<0>, cudaFuncAttributeMaxDynamicSharedMemorySize, T_SMEM);
    cudaFuncSetAttribute(gemm_mma<1>, cudaFuncAttributeMaxDynamicSharedMemorySize, T_SMEM);
    cudaFuncSetAttribute(conv_mma,    cudaFuncAttributeMaxDynamicSharedMemorySize, T_SMEM);

    setup_kernel<<<4961, 256>>>(W1, W2, cw);
    compact_stats_kernel<<<U_, 128>>>(z, ne, ln1_s, ln1_b);
    gemm_mma<0><<<dim3(4, 512), 256, T_SMEM>>>(b1, nullptr, nullptr);
    ln2cvt_kernel<<<U_, 128>>>(ln2_s, ln2_b);
    gemm_mma<1><<<dim3(2, 512), 256, T_SMEM>>>(b2, ux, uy);
    ln3_kernel<<<4096, 256>>>(ln3_s, ln3_b);
    conv_mma<<<dim3(2, 64), 256, T_SMEM>>>(cb, out);
}